// round 2
// baseline (speedup 1.0000x reference)
#include <cuda_runtime.h>
#include <cstdint>

typedef unsigned long long u64;

#define BATCH 16
#define D 512
#define LDIM 513
#define NITER2 64   // 64 iteration-pairs = 128 half-steps

// Scratch (static device arrays; no allocation)
__device__ float g_K[(size_t)BATCH * D * D];   // 16 MB: K = exp(symmetrized w0)
__device__ float g_qu[BATCH * D];              // q_128 = exp(-u_64)
__device__ float g_qv[BATCH * D];              // q_127 = exp(-v_64)

// ---------------------------------------------------------------------------
// Packed f32x2 helpers (FFMA2 in SASS — only reachable via PTX)
// ---------------------------------------------------------------------------
__device__ __forceinline__ u64 fma2(u64 a, u64 b, u64 c) {
    u64 d;
    asm("fma.rn.f32x2 %0, %1, %2, %3;" : "=l"(d) : "l"(a), "l"(b), "l"(c));
    return d;
}
__device__ __forceinline__ u64 mul2(u64 a, u64 b) {
    u64 d;
    asm("mul.rn.f32x2 %0, %1, %2;" : "=l"(d) : "l"(a), "l"(b));
    return d;
}

// ---------------------------------------------------------------------------
// Prep: K[b][i][j] = exp(0.5*(xp[b,1+i,1+j]+xp[b,1+j,1+i])), diag = exp(xu[b,1+i])
// ---------------------------------------------------------------------------
__global__ void prep_kernel(const float* __restrict__ xp,
                            const float* __restrict__ xu) {
    __shared__ float s[32][33];
    const int b  = blockIdx.z;
    const int it = blockIdx.y;
    const int jt = blockIdx.x;
    const int tx = threadIdx.x;      // 0..31
    const int ty = threadIdx.y;      // 0..7
    const float* xpb = xp + (size_t)b * LDIM * LDIM;

    #pragma unroll
    for (int k = 0; k < 32; k += 8) {
        int j = jt * 32 + ty + k;
        int i = it * 32 + tx;
        s[ty + k][tx] = xpb[(size_t)(1 + j) * LDIM + (1 + i)];
    }
    __syncthreads();

    float* Kb = g_K + (size_t)b * D * D;
    #pragma unroll
    for (int k = 0; k < 32; k += 8) {
        int i = it * 32 + ty + k;
        int j = jt * 32 + tx;
        float a = xpb[(size_t)(1 + i) * LDIM + (1 + j)];
        float t = s[tx][ty + k];
        float v = 0.5f * (a + t);
        if (i == j) v = xu[b * LDIM + 1 + i];
        Kb[(size_t)i * D + j] = expf(v);
    }
}

// ---------------------------------------------------------------------------
// One Sinkhorn half-step.
//   qsrc:      local shared copy of current q (read by all lanes)
//   qdst_base: smem byte address of the DESTINATION q buffer (base, row 0)
//   bar:       smem byte address of the mbarrier guarding the destination buffer
//   ph:        expected phase parity for this use of the barrier
//   row0:      this warp's first row (cluster-global, 0..511)
// Publishes: lane p (<8) stores this warp's 8 new q values into CTA p's
// destination buffer (2x st.shared::cluster.v4, release-ordered before its
// single remote mbarrier.arrive). All threads then wait on the local barrier.
// ---------------------------------------------------------------------------
__device__ __forceinline__ void halfstep(const u64 (&kf)[8][8],
                                         const float* qsrc,
                                         uint32_t qdst_base,
                                         uint32_t bar,
                                         int ph, int lane, int row0) {
    // q fragment for this lane's 16 columns, as 8 packed pairs
    const ulonglong2* qv = (const ulonglong2*)(qsrc + lane * 16);
    ulonglong2 t0 = qv[0], t1 = qv[1], t2 = qv[2], t3 = qv[3];
    u64 qp0 = t0.x, qp1 = t0.y, qp2 = t1.x, qp3 = t1.y;
    u64 qp4 = t2.x, qp5 = t2.y, qp6 = t3.x, qp7 = t3.y;

    float acc[8];
    #pragma unroll
    for (int r = 0; r < 8; r++) {
        u64 a = mul2(kf[r][0], qp0);
        a = fma2(kf[r][1], qp1, a);
        a = fma2(kf[r][2], qp2, a);
        a = fma2(kf[r][3], qp3, a);
        a = fma2(kf[r][4], qp4, a);
        a = fma2(kf[r][5], qp5, a);
        a = fma2(kf[r][6], qp6, a);
        a = fma2(kf[r][7], qp7, a);
        unsigned lo, hi;
        asm("mov.b64 {%0, %1}, %2;" : "=r"(lo), "=r"(hi) : "l"(a));
        acc[r] = __uint_as_float(lo) + __uint_as_float(hi);
    }

    // Butterfly reduction over 32 lanes (all lanes end with all 8 row sums)
    #pragma unroll
    for (int off = 16; off > 0; off >>= 1) {
        #pragma unroll
        for (int r = 0; r < 8; r++)
            acc[r] += __shfl_xor_sync(0xffffffffu, acc[r], off);
    }

    // Each lane inverts row (lane&7); gather all 8 inverses via shfl
    int rsel = lane & 7;
    float s = rsel == 0 ? acc[0] : rsel == 1 ? acc[1] :
              rsel == 2 ? acc[2] : rsel == 3 ? acc[3] :
              rsel == 4 ? acc[4] : rsel == 5 ? acc[5] :
              rsel == 6 ? acc[6] : acc[7];
    float inv = __fdividef(1.0f, s);
    float i0 = __shfl_sync(0xffffffffu, inv, 0);
    float i1 = __shfl_sync(0xffffffffu, inv, 1);
    float i2 = __shfl_sync(0xffffffffu, inv, 2);
    float i3 = __shfl_sync(0xffffffffu, inv, 3);
    float i4 = __shfl_sync(0xffffffffu, inv, 4);
    float i5 = __shfl_sync(0xffffffffu, inv, 5);
    float i6 = __shfl_sync(0xffffffffu, inv, 6);
    float i7 = __shfl_sync(0xffffffffu, inv, 7);

    if (lane < 8) {
        uint32_t dst = qdst_base + (uint32_t)row0 * 4u;
        uint32_t rd, rb;
        asm volatile("mapa.shared::cluster.u32 %0, %1, %2;"
                     : "=r"(rd) : "r"(dst), "r"(lane));
        asm volatile("st.shared::cluster.v4.f32 [%0], {%1, %2, %3, %4};"
                     :: "r"(rd), "f"(i0), "f"(i1), "f"(i2), "f"(i3) : "memory");
        asm volatile("st.shared::cluster.v4.f32 [%0], {%1, %2, %3, %4};"
                     :: "r"(rd + 16), "f"(i4), "f"(i5), "f"(i6), "f"(i7) : "memory");
        asm volatile("mapa.shared::cluster.u32 %0, %1, %2;"
                     : "=r"(rb) : "r"(bar), "r"(lane));
        asm volatile("mbarrier.arrive.release.cluster.shared::cluster.b64 _, [%0];"
                     :: "r"(rb) : "memory");
    }

    // Wait for all 64 arrivals (8 warps x 8 CTAs) on the local barrier
    unsigned done;
    asm volatile(
        "{\n\t.reg .pred p;\n\t"
        "mbarrier.try_wait.parity.acquire.cluster.shared::cta.b64 p, [%1], %2;\n\t"
        "selp.b32 %0, 1, 0, p;\n\t}"
        : "=r"(done) : "r"(bar), "r"((unsigned)ph) : "memory");
    while (!done) {
        asm volatile(
            "{\n\t.reg .pred p;\n\t"
            "mbarrier.try_wait.parity.acquire.cluster.shared::cta.b64 p, [%1], %2, 0x989680;\n\t"
            "selp.b32 %0, 1, 0, p;\n\t}"
            : "=r"(done) : "r"(bar), "r"((unsigned)ph) : "memory");
    }
}

// ---------------------------------------------------------------------------
// Persistent iteration kernel: one 8-CTA cluster per batch, 256 thr/CTA.
// K register-resident as packed f32x2 pairs (8 rows x 8 pairs per lane).
// ---------------------------------------------------------------------------
__global__ void __launch_bounds__(256, 1) iter_kernel() {
    __shared__ __align__(16) float qbuf0[D];
    __shared__ __align__(16) float qbuf1[D];
    __shared__ __align__(8) u64 barmem[2];

    unsigned rank;
    asm("mov.u32 %0, %%cluster_ctarank;" : "=r"(rank));
    const int batch = blockIdx.x >> 3;
    const int tid   = threadIdx.x;
    const int wid   = tid >> 5;
    const int lane  = tid & 31;
    const int row0  = (int)rank * 64 + wid * 8;

    // Load K fragment: rows [row0, row0+8), cols [lane*16, lane*16+16)
    u64 kf[8][8];
    const float* Kb = g_K + (size_t)batch * D * D;
    #pragma unroll
    for (int r = 0; r < 8; r++) {
        const ulonglong2* rp =
            (const ulonglong2*)(Kb + (size_t)(row0 + r) * D + lane * 16);
        #pragma unroll
        for (int c = 0; c < 4; c++) {
            ulonglong2 t = rp[c];
            kf[r][2 * c]     = t.x;
            kf[r][2 * c + 1] = t.y;
        }
    }

    qbuf0[tid]       = 1.0f;
    qbuf0[tid + 256] = 1.0f;

    const uint32_t q0 = (uint32_t)__cvta_generic_to_shared(qbuf0);
    const uint32_t q1 = (uint32_t)__cvta_generic_to_shared(qbuf1);
    const uint32_t b0 = (uint32_t)__cvta_generic_to_shared(&barmem[0]);
    const uint32_t b1 = (uint32_t)__cvta_generic_to_shared(&barmem[1]);

    if (tid == 0) {
        asm volatile("mbarrier.init.shared.b64 [%0], 64;" :: "r"(b0) : "memory");
        asm volatile("mbarrier.init.shared.b64 [%0], 64;" :: "r"(b1) : "memory");
        asm volatile("fence.mbarrier_init.release.cluster;" ::: "memory");
    }
    __syncthreads();
    asm volatile("barrier.cluster.arrive.aligned;\n\t"
                 "barrier.cluster.wait.aligned;" ::: "memory");

    #pragma unroll 1
    for (int it2 = 0; it2 < NITER2; it2++) {
        int ph = it2 & 1;
        halfstep(kf, qbuf0, q1, b1, ph, lane, row0);  // read q0 -> publish q1
        halfstep(kf, qbuf1, q0, b0, ph, lane, row0);  // read q1 -> publish q0
    }

    // qbuf0 = q_128 = exp(-u_64);  qbuf1 = q_127 = exp(-v_64)
    if (tid < 64) {
        int row = (int)rank * 64 + tid;
        g_qu[batch * D + row] = qbuf0[row];
        g_qv[batch * D + row] = qbuf1[row];
    }

    // No CTA may exit while cluster peers could still target its SMEM
    asm volatile("barrier.cluster.arrive.aligned;\n\t"
                 "barrier.cluster.wait.aligned;" ::: "memory");
}

// ---------------------------------------------------------------------------
// Writeback: xp output [0, 16*513*513) then xu output [.., +16*513)
// ---------------------------------------------------------------------------
__global__ void out_kernel(const float* __restrict__ xp,
                           const float* __restrict__ xu,
                           float* __restrict__ out) {
    int idx = blockIdx.x * blockDim.x + threadIdx.x;
    const int T1 = BATCH * LDIM * LDIM;
    const int T2 = BATCH * LDIM;
    if (idx < T1) {
        int b   = idx / (LDIM * LDIM);
        int rem = idx - b * (LDIM * LDIM);
        int i = rem / LDIM;
        int j = rem - i * LDIM;
        float v;
        if (i == 0 && j == 0)       v = expf(xp[idx]);
        else if (i == 0 || j == 0)  v = xp[idx];
        else if (i == j)            v = 0.0f;
        else {
            v = g_K[((size_t)b * D + (i - 1)) * D + (j - 1)]
                * g_qu[b * D + i - 1] * g_qv[b * D + j - 1];
        }
        out[idx] = v;
    } else if (idx < T1 + T2) {
        int k = idx - T1;
        int b = k / LDIM;
        int i = k - b * LDIM;
        float v;
        if (i == 0) v = expf(xu[k]);
        else {
            int d = i - 1;
            v = g_K[((size_t)b * D + d) * D + d]
                * g_qu[b * D + d] * g_qv[b * D + d];
        }
        out[idx] = v;
    }
}

// ---------------------------------------------------------------------------
extern "C" void kernel_launch(void* const* d_in, const int* in_sizes, int n_in,
                              void* d_out, int out_size) {
    const float* xp;
    const float* xu;
    if (in_sizes[0] >= in_sizes[1]) { xp = (const float*)d_in[0]; xu = (const float*)d_in[1]; }
    else                            { xp = (const float*)d_in[1]; xu = (const float*)d_in[0]; }
    float* out = (float*)d_out;

    // 1) Build K = exp(symmetrized w0)
    dim3 pb(32, 8), pg(D / 32, D / 32, BATCH);
    prep_kernel<<<pg, pb>>>(xp, xu);

    // 2) 128 Sinkhorn half-steps, one 8-CTA cluster per batch
    cudaLaunchConfig_t cfg = {};
    cfg.gridDim  = dim3(BATCH * 8);
    cfg.blockDim = dim3(256);
    cfg.dynamicSmemBytes = 0;
    cfg.stream = 0;
    cudaLaunchAttribute attrs[1];
    attrs[0].id = cudaLaunchAttributeClusterDimension;
    attrs[0].val.clusterDim.x = 8;
    attrs[0].val.clusterDim.y = 1;
    attrs[0].val.clusterDim.z = 1;
    cfg.attrs = attrs;
    cfg.numAttrs = 1;
    cudaLaunchKernelEx(&cfg, iter_kernel);

    // 3) Writeback (single kernel)
    const int total = BATCH * LDIM * LDIM + BATCH * LDIM;
    out_kernel<<<(total + 255) / 256, 256>>>(xp, xu, out);
}

// round 3
// speedup vs baseline: 1.4710x; 1.4710x over previous
#include <cuda_runtime.h>
#include <cstdint>

#define BATCH 16
#define D 512
#define LDIM 513
#define NITER2 64   // 64 iteration-pairs = 128 half-steps

// Scratch (static device arrays; no allocation)
__device__ float g_K[(size_t)BATCH * D * D];   // 16 MB: K = exp(symmetrized w0)
__device__ float g_qu[BATCH * D];              // q_128 = exp(-u_64)
__device__ float g_qv[BATCH * D];              // q_127 = exp(-v_64)

// ---------------------------------------------------------------------------
// Prep: K[b][i][j] = exp(0.5*(xp[b,1+i,1+j]+xp[b,1+j,1+i])), diag = exp(xu[b,1+i])
// ---------------------------------------------------------------------------
__global__ void prep_kernel(const float* __restrict__ xp,
                            const float* __restrict__ xu) {
    __shared__ float s[32][33];
    const int b  = blockIdx.z;
    const int it = blockIdx.y;
    const int jt = blockIdx.x;
    const int tx = threadIdx.x;      // 0..31
    const int ty = threadIdx.y;      // 0..7
    const float* xpb = xp + (size_t)b * LDIM * LDIM;

    #pragma unroll
    for (int k = 0; k < 32; k += 8) {
        int j = jt * 32 + ty + k;
        int i = it * 32 + tx;
        s[ty + k][tx] = xpb[(size_t)(1 + j) * LDIM + (1 + i)];
    }
    __syncthreads();

    float* Kb = g_K + (size_t)b * D * D;
    #pragma unroll
    for (int k = 0; k < 32; k += 8) {
        int i = it * 32 + ty + k;
        int j = jt * 32 + tx;
        float a = xpb[(size_t)(1 + i) * LDIM + (1 + j)];
        float t = s[tx][ty + k];
        float v = 0.5f * (a + t);
        if (i == j) v = xu[b * LDIM + 1 + i];
        Kb[(size_t)i * D + j] = expf(v);
    }
}

// ---------------------------------------------------------------------------
// One Sinkhorn half-step.
//   kf:        K fragment, kf[r][k] = K[row0+r][lane + 32k]
//   qsrc:      local shared copy of current q
//   qdst_base: smem byte address of the DESTINATION q buffer (row 0)
//   lane/row0: lane id and this warp's first row (cluster-global)
// Ends with a full cluster barrier (release/acquire semantics order the
// remote shared::cluster stores).
// ---------------------------------------------------------------------------
__device__ __forceinline__ void halfstep(const float (&kf)[8][16],
                                         const float* __restrict__ qsrc,
                                         uint32_t qdst_base,
                                         int lane, int row0) {
    // Conflict-free q loads: lane l reads q[l + 32k] (bank == lane)
    float qv[16];
    #pragma unroll
    for (int k = 0; k < 16; k++) qv[k] = qsrc[lane + 32 * k];

    float acc[8];
    #pragma unroll
    for (int r = 0; r < 8; r++) {
        float s0 = kf[r][0] * qv[0];
        float s1 = kf[r][1] * qv[1];
        float s2 = kf[r][2] * qv[2];
        float s3 = kf[r][3] * qv[3];
        #pragma unroll
        for (int k = 4; k < 16; k += 4) {
            s0 = fmaf(kf[r][k + 0], qv[k + 0], s0);
            s1 = fmaf(kf[r][k + 1], qv[k + 1], s1);
            s2 = fmaf(kf[r][k + 2], qv[k + 2], s2);
            s3 = fmaf(kf[r][k + 3], qv[k + 3], s3);
        }
        acc[r] = (s0 + s1) + (s2 + s3);
    }

    // Folded reduction: exchange only the half being discarded.
    // After stage 3, each lane holds the 32-lane-complete partial for
    // row (lane>>2)&7; stages 4/5 finish within the 4-lane group.
    const unsigned FULL = 0xffffffffu;
    bool hi4 = (lane & 16) != 0;
    float v[4];
    #pragma unroll
    for (int i = 0; i < 4; i++) {
        float t = hi4 ? acc[i] : acc[4 + i];
        float r = __shfl_xor_sync(FULL, t, 16);
        v[i] = (hi4 ? acc[4 + i] : acc[i]) + r;
    }
    bool hi3 = (lane & 8) != 0;
    float w[2];
    #pragma unroll
    for (int i = 0; i < 2; i++) {
        float t = hi3 ? v[i] : v[2 + i];
        float r = __shfl_xor_sync(FULL, t, 8);
        w[i] = (hi3 ? v[2 + i] : v[i]) + r;
    }
    bool hi2 = (lane & 4) != 0;
    {
        float t = hi2 ? w[0] : w[1];
        float r = __shfl_xor_sync(FULL, t, 4);
        w[0] = (hi2 ? w[1] : w[0]) + r;
    }
    float s = w[0];
    s += __shfl_xor_sync(FULL, s, 2);
    s += __shfl_xor_sync(FULL, s, 1);
    // s = full row sum for row (lane>>2)&7

    float inv = __fdividef(1.0f, s);
    float i0 = __shfl_sync(FULL, inv, 0);
    float i1 = __shfl_sync(FULL, inv, 4);
    float i2 = __shfl_sync(FULL, inv, 8);
    float i3 = __shfl_sync(FULL, inv, 12);
    float i4 = __shfl_sync(FULL, inv, 16);
    float i5 = __shfl_sync(FULL, inv, 20);
    float i6 = __shfl_sync(FULL, inv, 24);
    float i7 = __shfl_sync(FULL, inv, 28);

    // Lane p (<8) publishes this warp's 8 new q values to CTA p
    if (lane < 8) {
        uint32_t dst = qdst_base + (uint32_t)row0 * 4u;
        uint32_t rd;
        asm volatile("mapa.shared::cluster.u32 %0, %1, %2;"
                     : "=r"(rd) : "r"(dst), "r"(lane));
        asm volatile("st.shared::cluster.v4.f32 [%0], {%1, %2, %3, %4};"
                     :: "r"(rd), "f"(i0), "f"(i1), "f"(i2), "f"(i3) : "memory");
        asm volatile("st.shared::cluster.v4.f32 [%0], {%1, %2, %3, %4};"
                     :: "r"(rd + 16), "f"(i4), "f"(i5), "f"(i6), "f"(i7) : "memory");
    }

    // Cluster barrier (arrive=release, wait=acquire -> remote stores visible)
    asm volatile("barrier.cluster.arrive.aligned;\n\t"
                 "barrier.cluster.wait.aligned;" ::: "memory");
}

// ---------------------------------------------------------------------------
// Persistent iteration kernel: one 8-CTA cluster per batch, 256 thr/CTA.
// Each CTA owns 64 rows; each warp 8 rows; lane l owns cols {l+32k}.
// ---------------------------------------------------------------------------
__global__ void __launch_bounds__(256, 1) iter_kernel() {
    __shared__ __align__(16) float qbuf0[D];
    __shared__ __align__(16) float qbuf1[D];

    unsigned rank;
    asm("mov.u32 %0, %%cluster_ctarank;" : "=r"(rank));
    const int batch = blockIdx.x >> 3;
    const int tid   = threadIdx.x;
    const int wid   = tid >> 5;
    const int lane  = tid & 31;
    const int row0  = (int)rank * 64 + wid * 8;

    // K fragment: kf[r][k] = K[row0+r][lane + 32k]  (coalesced per (r,k))
    float kf[8][16];
    const float* Kb = g_K + (size_t)batch * D * D;
    #pragma unroll
    for (int r = 0; r < 8; r++) {
        const float* rp = Kb + (size_t)(row0 + r) * D + lane;
        #pragma unroll
        for (int k = 0; k < 16; k++) kf[r][k] = rp[32 * k];
    }

    qbuf0[tid]       = 1.0f;
    qbuf0[tid + 256] = 1.0f;

    const uint32_t q0 = (uint32_t)__cvta_generic_to_shared(qbuf0);
    const uint32_t q1 = (uint32_t)__cvta_generic_to_shared(qbuf1);

    __syncthreads();
    asm volatile("barrier.cluster.arrive.aligned;\n\t"
                 "barrier.cluster.wait.aligned;" ::: "memory");

    #pragma unroll 1
    for (int it2 = 0; it2 < NITER2; it2++) {
        halfstep(kf, qbuf0, q1, lane, row0);  // read q0 -> publish q1
        halfstep(kf, qbuf1, q0, lane, row0);  // read q1 -> publish q0
    }

    // qbuf0 = q_128 = exp(-u_64);  qbuf1 = q_127 = exp(-v_64)
    if (tid < 64) {
        int row = (int)rank * 64 + tid;
        g_qu[batch * D + row] = qbuf0[row];
        g_qv[batch * D + row] = qbuf1[row];
    }

    // No CTA may exit while cluster peers could still target its SMEM
    asm volatile("barrier.cluster.arrive.aligned;\n\t"
                 "barrier.cluster.wait.aligned;" ::: "memory");
}

// ---------------------------------------------------------------------------
// Writeback: xp output [0, 16*513*513) then xu output [.., +16*513)
// ---------------------------------------------------------------------------
__global__ void out_kernel(const float* __restrict__ xp,
                           const float* __restrict__ xu,
                           float* __restrict__ out) {
    int idx = blockIdx.x * blockDim.x + threadIdx.x;
    const int T1 = BATCH * LDIM * LDIM;
    const int T2 = BATCH * LDIM;
    if (idx < T1) {
        int b   = idx / (LDIM * LDIM);
        int rem = idx - b * (LDIM * LDIM);
        int i = rem / LDIM;
        int j = rem - i * LDIM;
        float v;
        if (i == 0 && j == 0)       v = expf(xp[idx]);
        else if (i == 0 || j == 0)  v = xp[idx];
        else if (i == j)            v = 0.0f;
        else {
            v = g_K[((size_t)b * D + (i - 1)) * D + (j - 1)]
                * g_qu[b * D + i - 1] * g_qv[b * D + j - 1];
        }
        out[idx] = v;
    } else if (idx < T1 + T2) {
        int k = idx - T1;
        int b = k / LDIM;
        int i = k - b * LDIM;
        float v;
        if (i == 0) v = expf(xu[k]);
        else {
            int d = i - 1;
            v = g_K[((size_t)b * D + d) * D + d]
                * g_qu[b * D + d] * g_qv[b * D + d];
        }
        out[idx] = v;
    }
}

// ---------------------------------------------------------------------------
extern "C" void kernel_launch(void* const* d_in, const int* in_sizes, int n_in,
                              void* d_out, int out_size) {
    const float* xp;
    const float* xu;
    if (in_sizes[0] >= in_sizes[1]) { xp = (const float*)d_in[0]; xu = (const float*)d_in[1]; }
    else                            { xp = (const float*)d_in[1]; xu = (const float*)d_in[0]; }
    float* out = (float*)d_out;

    // 1) Build K = exp(symmetrized w0)
    dim3 pb(32, 8), pg(D / 32, D / 32, BATCH);
    prep_kernel<<<pg, pb>>>(xp, xu);

    // 2) 128 Sinkhorn half-steps, one 8-CTA cluster per batch
    cudaLaunchConfig_t cfg = {};
    cfg.gridDim  = dim3(BATCH * 8);
    cfg.blockDim = dim3(256);
    cfg.dynamicSmemBytes = 0;
    cfg.stream = 0;
    cudaLaunchAttribute attrs[1];
    attrs[0].id = cudaLaunchAttributeClusterDimension;
    attrs[0].val.clusterDim.x = 8;
    attrs[0].val.clusterDim.y = 1;
    attrs[0].val.clusterDim.z = 1;
    cfg.attrs = attrs;
    cfg.numAttrs = 1;
    cudaLaunchKernelEx(&cfg, iter_kernel);

    // 3) Writeback (single kernel)
    const int total = BATCH * LDIM * LDIM + BATCH * LDIM;
    out_kernel<<<(total + 255) / 256, 256>>>(xp, xu, out);
}

// round 4
// speedup vs baseline: 1.5407x; 1.0474x over previous
#include <cuda_runtime.h>
#include <cstdint>

typedef unsigned long long u64;

#define BATCH 16
#define D 512
#define LDIM 513
#define NITER2 64   // 64 iteration-pairs = 128 half-steps

__device__ float g_K[(size_t)BATCH * D * D];   // 16 MB: K = exp(symmetrized w0)
__device__ float g_qu[BATCH * D];
__device__ float g_qv[BATCH * D];

// ---------------------------------------------------------------------------
// Packed f32x2 helpers
// ---------------------------------------------------------------------------
__device__ __forceinline__ u64 fma2(u64 a, u64 b, u64 c) {
    u64 d;
    asm("fma.rn.f32x2 %0, %1, %2, %3;" : "=l"(d) : "l"(a), "l"(b), "l"(c));
    return d;
}
__device__ __forceinline__ u64 mul2(u64 a, u64 b) {
    u64 d;
    asm("mul.rn.f32x2 %0, %1, %2;" : "=l"(d) : "l"(a), "l"(b));
    return d;
}
__device__ __forceinline__ u64 pack2(float x, float y) {
    u64 d;
    asm("mov.b64 %0, {%1, %2};" : "=l"(d) : "f"(x), "f"(y));
    return d;
}

// ---------------------------------------------------------------------------
// Prep: K[b][i][j] = exp(0.5*(xp[b,1+i,1+j]+xp[b,1+j,1+i])), diag = exp(xu[b,1+i])
// ---------------------------------------------------------------------------
__global__ void prep_kernel(const float* __restrict__ xp,
                            const float* __restrict__ xu) {
    __shared__ float s[32][33];
    const int b  = blockIdx.z;
    const int it = blockIdx.y;
    const int jt = blockIdx.x;
    const int tx = threadIdx.x;
    const int ty = threadIdx.y;
    const float* xpb = xp + (size_t)b * LDIM * LDIM;

    #pragma unroll
    for (int k = 0; k < 32; k += 8) {
        int j = jt * 32 + ty + k;
        int i = it * 32 + tx;
        s[ty + k][tx] = xpb[(size_t)(1 + j) * LDIM + (1 + i)];
    }
    __syncthreads();

    float* Kb = g_K + (size_t)b * D * D;
    #pragma unroll
    for (int k = 0; k < 32; k += 8) {
        int i = it * 32 + ty + k;
        int j = jt * 32 + tx;
        float a = xpb[(size_t)(1 + i) * LDIM + (1 + j)];
        float t = s[tx][ty + k];
        float v = 0.5f * (a + t);
        if (i == j) v = xu[b * LDIM + 1 + i];
        Kb[(size_t)i * D + j] = expf(v);
    }
}

// ---------------------------------------------------------------------------
// One Sinkhorn half-step.
//   kf[r][m] = packed pair K[row0+r][2*lane + 64m .. +1]
//   qsrc:     local shared copy of current q (full 512)
//   qdst:     LOCAL destination q buffer (generic pointer)
//   qdst_sm:  smem byte address of destination buffer (for mapa)
//   bar:      smem byte address of local mbarrier guarding destination
//   ph:       expected phase parity
// ---------------------------------------------------------------------------
__device__ __forceinline__ void halfstep(const u64 (&kf)[8][8],
                                         const float* __restrict__ qsrc,
                                         float* __restrict__ qdst,
                                         uint32_t qdst_sm, uint32_t bar,
                                         int ph, int lane, int wid,
                                         unsigned rank, int row0) {
    // q pairs: lane owns cols {2*lane+64m, 2*lane+64m+1} — conflict-free v2 LDS
    const float2* qp = (const float2*)qsrc + lane;
    u64 qv[8];
    #pragma unroll
    for (int m = 0; m < 8; m++) {
        float2 t = qp[32 * m];
        qv[m] = pack2(t.x, t.y);
    }

    float acc[8];
    #pragma unroll
    for (int r = 0; r < 8; r++) {
        u64 a = mul2(kf[r][0], qv[0]);
        a = fma2(kf[r][1], qv[1], a);
        a = fma2(kf[r][2], qv[2], a);
        a = fma2(kf[r][3], qv[3], a);
        a = fma2(kf[r][4], qv[4], a);
        a = fma2(kf[r][5], qv[5], a);
        a = fma2(kf[r][6], qv[6], a);
        a = fma2(kf[r][7], qv[7], a);
        unsigned lo, hi;
        asm("mov.b64 {%0, %1}, %2;" : "=r"(lo), "=r"(hi) : "l"(a));
        acc[r] = __uint_as_float(lo) + __uint_as_float(hi);
    }

    // Folded butterfly: after 3 stages each lane holds the 32-lane partial
    // for row (lane>>2)&7; last 2 stages finish within the 4-lane group.
    const unsigned FULL = 0xffffffffu;
    bool hi4 = (lane & 16) != 0;
    float v[4];
    #pragma unroll
    for (int i = 0; i < 4; i++) {
        float t = hi4 ? acc[i] : acc[4 + i];
        float r = __shfl_xor_sync(FULL, t, 16);
        v[i] = (hi4 ? acc[4 + i] : acc[i]) + r;
    }
    bool hi3 = (lane & 8) != 0;
    float w[2];
    #pragma unroll
    for (int i = 0; i < 2; i++) {
        float t = hi3 ? v[i] : v[2 + i];
        float r = __shfl_xor_sync(FULL, t, 8);
        w[i] = (hi3 ? v[2 + i] : v[i]) + r;
    }
    bool hi2 = (lane & 4) != 0;
    {
        float t = hi2 ? w[0] : w[1];
        float r = __shfl_xor_sync(FULL, t, 4);
        w[0] = (hi2 ? w[1] : w[0]) + r;
    }
    float s = w[0];
    s += __shfl_xor_sync(FULL, s, 2);
    s += __shfl_xor_sync(FULL, s, 1);

    float inv = __fdividef(1.0f, s);

    // Stage locally: lanes 0,4,...,28 write rows row0..row0+7 (distinct banks)
    if ((lane & 3) == 0)
        qdst[row0 + (lane >> 2)] = inv;

    __syncthreads();

    // Copy warp `wid` ships this CTA's 64 fresh rows to cluster CTA `wid`,
    // then lane 0 release-arrives on that CTA's barrier (orders OWN stores;
    // values were read from local smem after bar.sync -> in registers).
    {
        float2 val = *(const float2*)(qdst + (rank * 64 + lane * 2));
        uint32_t dst = qdst_sm + (rank * 64u + (unsigned)lane * 2u) * 4u;
        uint32_t rd, rb;
        asm volatile("mapa.shared::cluster.u32 %0, %1, %2;"
                     : "=r"(rd) : "r"(dst), "r"(wid));
        asm volatile("st.shared::cluster.v2.f32 [%0], {%1, %2};"
                     :: "r"(rd), "f"(val.x), "f"(val.y) : "memory");
        if (lane == 0) {
            asm volatile("mapa.shared::cluster.u32 %0, %1, %2;"
                         : "=r"(rb) : "r"(bar), "r"(wid));
            asm volatile("mbarrier.arrive.release.cluster.shared::cluster.b64 _, [%0];"
                         :: "r"(rb) : "memory");
        }
    }

    // Wait for all 8 source CTAs
    unsigned done;
    asm volatile(
        "{\n\t.reg .pred p;\n\t"
        "mbarrier.try_wait.parity.acquire.cluster.shared::cta.b64 p, [%1], %2;\n\t"
        "selp.b32 %0, 1, 0, p;\n\t}"
        : "=r"(done) : "r"(bar), "r"((unsigned)ph) : "memory");
    while (!done) {
        asm volatile(
            "{\n\t.reg .pred p;\n\t"
            "mbarrier.try_wait.parity.acquire.cluster.shared::cta.b64 p, [%1], %2, 0x989680;\n\t"
            "selp.b32 %0, 1, 0, p;\n\t}"
            : "=r"(done) : "r"(bar), "r"((unsigned)ph) : "memory");
    }
}

// ---------------------------------------------------------------------------
// Persistent iteration kernel: one 8-CTA cluster per batch, 256 thr/CTA.
// ---------------------------------------------------------------------------
__global__ void __launch_bounds__(256, 1) iter_kernel() {
    __shared__ __align__(16) float qbuf0[D];
    __shared__ __align__(16) float qbuf1[D];
    __shared__ __align__(8) u64 barmem[2];

    unsigned rank;
    asm("mov.u32 %0, %%cluster_ctarank;" : "=r"(rank));
    const int batch = blockIdx.x >> 3;
    const int tid   = threadIdx.x;
    const int wid   = tid >> 5;
    const int lane  = tid & 31;
    const int row0  = (int)rank * 64 + wid * 8;

    // K fragment as packed pairs: kf[r][m] = K[row0+r][2*lane + 64m .. +1]
    u64 kf[8][8];
    const float* Kb = g_K + (size_t)batch * D * D;
    #pragma unroll
    for (int r = 0; r < 8; r++) {
        const float2* rp = (const float2*)(Kb + (size_t)(row0 + r) * D) + lane;
        #pragma unroll
        for (int m = 0; m < 8; m++) {
            float2 t = rp[32 * m];
            kf[r][m] = pack2(t.x, t.y);
        }
    }

    qbuf0[tid]       = 1.0f;
    qbuf0[tid + 256] = 1.0f;

    const uint32_t q0 = (uint32_t)__cvta_generic_to_shared(qbuf0);
    const uint32_t q1 = (uint32_t)__cvta_generic_to_shared(qbuf1);
    const uint32_t b0 = (uint32_t)__cvta_generic_to_shared(&barmem[0]);
    const uint32_t b1 = (uint32_t)__cvta_generic_to_shared(&barmem[1]);

    if (tid == 0) {
        asm volatile("mbarrier.init.shared.b64 [%0], 8;" :: "r"(b0) : "memory");
        asm volatile("mbarrier.init.shared.b64 [%0], 8;" :: "r"(b1) : "memory");
        asm volatile("fence.mbarrier_init.release.cluster;" ::: "memory");
    }
    __syncthreads();
    asm volatile("barrier.cluster.arrive.aligned;\n\t"
                 "barrier.cluster.wait.aligned;" ::: "memory");

    #pragma unroll 1
    for (int it2 = 0; it2 < NITER2; it2++) {
        int ph = it2 & 1;
        halfstep(kf, qbuf0, qbuf1, q1, b1, ph, lane, wid, rank, row0);
        halfstep(kf, qbuf1, qbuf0, q0, b0, ph, lane, wid, rank, row0);
    }

    // qbuf0 = q_128 = exp(-u_64);  qbuf1 = q_127 = exp(-v_64)
    if (tid < 64) {
        int row = (int)rank * 64 + tid;
        g_qu[batch * D + row] = qbuf0[row];
        g_qv[batch * D + row] = qbuf1[row];
    }

    asm volatile("barrier.cluster.arrive.aligned;\n\t"
                 "barrier.cluster.wait.aligned;" ::: "memory");
}

// ---------------------------------------------------------------------------
// Writeback: xp output [0, 16*513*513) then xu output [.., +16*513)
// ---------------------------------------------------------------------------
__global__ void out_kernel(const float* __restrict__ xp,
                           const float* __restrict__ xu,
                           float* __restrict__ out) {
    int idx = blockIdx.x * blockDim.x + threadIdx.x;
    const int T1 = BATCH * LDIM * LDIM;
    const int T2 = BATCH * LDIM;
    if (idx < T1) {
        int b   = idx / (LDIM * LDIM);
        int rem = idx - b * (LDIM * LDIM);
        int i = rem / LDIM;
        int j = rem - i * LDIM;
        float v;
        if (i == 0 && j == 0)       v = expf(xp[idx]);
        else if (i == 0 || j == 0)  v = xp[idx];
        else if (i == j)            v = 0.0f;
        else {
            v = g_K[((size_t)b * D + (i - 1)) * D + (j - 1)]
                * g_qu[b * D + i - 1] * g_qv[b * D + j - 1];
        }
        out[idx] = v;
    } else if (idx < T1 + T2) {
        int k = idx - T1;
        int b = k / LDIM;
        int i = k - b * LDIM;
        float v;
        if (i == 0) v = expf(xu[k]);
        else {
            int d = i - 1;
            v = g_K[((size_t)b * D + d) * D + d]
                * g_qu[b * D + d] * g_qv[b * D + d];
        }
        out[idx] = v;
    }
}

// ---------------------------------------------------------------------------
extern "C" void kernel_launch(void* const* d_in, const int* in_sizes, int n_in,
                              void* d_out, int out_size) {
    const float* xp;
    const float* xu;
    if (in_sizes[0] >= in_sizes[1]) { xp = (const float*)d_in[0]; xu = (const float*)d_in[1]; }
    else                            { xp = (const float*)d_in[1]; xu = (const float*)d_in[0]; }
    float* out = (float*)d_out;

    dim3 pb(32, 8), pg(D / 32, D / 32, BATCH);
    prep_kernel<<<pg, pb>>>(xp, xu);

    cudaLaunchConfig_t cfg = {};
    cfg.gridDim  = dim3(BATCH * 8);
    cfg.blockDim = dim3(256);
    cfg.dynamicSmemBytes = 0;
    cfg.stream = 0;
    cudaLaunchAttribute attrs[1];
    attrs[0].id = cudaLaunchAttributeClusterDimension;
    attrs[0].val.clusterDim.x = 8;
    attrs[0].val.clusterDim.y = 1;
    attrs[0].val.clusterDim.z = 1;
    cfg.attrs = attrs;
    cfg.numAttrs = 1;
    cudaLaunchKernelEx(&cfg, iter_kernel);

    const int total = BATCH * LDIM * LDIM + BATCH * LDIM;
    out_kernel<<<(total + 255) / 256, 256>>>(xp, xu, out);
}

// round 5
// speedup vs baseline: 2.0723x; 1.3450x over previous
#include <cuda_runtime.h>
#include <cstdint>

typedef unsigned long long u64;

#define BATCH 16
#define D 512
#define LDIM 513
#define NITER2 64   // 64 iteration-pairs = 128 half-steps

__device__ float g_K[(size_t)BATCH * D * D];   // K = exp(symmetrized w0), for writeback
__device__ float g_qu[BATCH * D];
__device__ float g_qv[BATCH * D];

// ---------------------------------------------------------------------------
// Packed f32x2 helpers
// ---------------------------------------------------------------------------
__device__ __forceinline__ u64 fma2(u64 a, u64 b, u64 c) {
    u64 d;
    asm("fma.rn.f32x2 %0, %1, %2, %3;" : "=l"(d) : "l"(a), "l"(b), "l"(c));
    return d;
}
__device__ __forceinline__ u64 pack2(float x, float y) {
    u64 d;
    asm("mov.b64 %0, {%1, %2};" : "=l"(d) : "f"(x), "f"(y));
    return d;
}

// try_wait (acquire, cluster scope) with sleep-hint poll loop
__device__ __forceinline__ void bar_wait(uint32_t bar, unsigned ph) {
    unsigned done;
    asm volatile(
        "{\n\t.reg .pred p;\n\t"
        "mbarrier.try_wait.parity.acquire.cluster.shared::cta.b64 p, [%1], %2;\n\t"
        "selp.b32 %0, 1, 0, p;\n\t}"
        : "=r"(done) : "r"(bar), "r"(ph) : "memory");
    while (!done) {
        asm volatile(
            "{\n\t.reg .pred p;\n\t"
            "mbarrier.try_wait.parity.acquire.cluster.shared::cta.b64 p, [%1], %2, 0x989680;\n\t"
            "selp.b32 %0, 1, 0, p;\n\t}"
            : "=r"(done) : "r"(bar), "r"(ph) : "memory");
    }
}

// ---------------------------------------------------------------------------
// One half-step: acc = K_frag * q, pipelined over 2 barrier groups.
//   barA_r/barB_r: read-buffer barriers (A: segments 0-3, B: 4-7)
//   do_wait=false only for the very first half-step (q = ones, no producers)
//   Publish: st.async v2 -> every CTA's write buffer + its A/B barrier.
// ---------------------------------------------------------------------------
__device__ __forceinline__ void halfstep(const u64 (&kf)[8][8],
                                         const float* __restrict__ qsrc,
                                         uint32_t barA_r, uint32_t barB_r,
                                         unsigned ph, bool do_wait,
                                         uint32_t qdst_sm,
                                         uint32_t barA_w, uint32_t barB_w,
                                         int tid, int lane,
                                         unsigned rank, int row0) {
    // Post expected-tx for this phase (one thread; the expect IS the arrive)
    if (do_wait && tid == 0) {
        asm volatile("mbarrier.arrive.expect_tx.shared.b64 _, [%0], 1024;"
                     :: "r"(barA_r) : "memory");
        asm volatile("mbarrier.arrive.expect_tx.shared.b64 _, [%0], 1024;"
                     :: "r"(barB_r) : "memory");
    }

    u64 acc64[8];
    #pragma unroll
    for (int r = 0; r < 8; r++) acc64[r] = 0ULL;

    if (do_wait) bar_wait(barA_r, ph);
    #pragma unroll
    for (int m = 0; m < 4; m++) {
        float2 qq = *(const float2*)(qsrc + m * 64 + 2 * lane);
        u64 qp = pack2(qq.x, qq.y);
        #pragma unroll
        for (int r = 0; r < 8; r++) acc64[r] = fma2(kf[r][m], qp, acc64[r]);
    }
    if (do_wait) bar_wait(barB_r, ph);
    #pragma unroll
    for (int m = 4; m < 8; m++) {
        float2 qq = *(const float2*)(qsrc + m * 64 + 2 * lane);
        u64 qp = pack2(qq.x, qq.y);
        #pragma unroll
        for (int r = 0; r < 8; r++) acc64[r] = fma2(kf[r][m], qp, acc64[r]);
    }

    float acc[8];
    #pragma unroll
    for (int r = 0; r < 8; r++) {
        unsigned lo, hi;
        asm("mov.b64 {%0, %1}, %2;" : "=r"(lo), "=r"(hi) : "l"(acc64[r]));
        acc[r] = __uint_as_float(lo) + __uint_as_float(hi);
    }

    // Folded butterfly: lane ends with full sum for row (lane>>2)&7
    const unsigned FULL = 0xffffffffu;
    bool hi4 = (lane & 16) != 0;
    float v[4];
    #pragma unroll
    for (int i = 0; i < 4; i++) {
        float t = hi4 ? acc[i] : acc[4 + i];
        float r = __shfl_xor_sync(FULL, t, 16);
        v[i] = (hi4 ? acc[4 + i] : acc[i]) + r;
    }
    bool hi3 = (lane & 8) != 0;
    float w[2];
    #pragma unroll
    for (int i = 0; i < 2; i++) {
        float t = hi3 ? v[i] : v[2 + i];
        float r = __shfl_xor_sync(FULL, t, 8);
        w[i] = (hi3 ? v[2 + i] : v[i]) + r;
    }
    bool hi2 = (lane & 4) != 0;
    {
        float t = hi2 ? w[0] : w[1];
        float r = __shfl_xor_sync(FULL, t, 4);
        w[0] = (hi2 ? w[1] : w[0]) + r;
    }
    float s = w[0];
    s += __shfl_xor_sync(FULL, s, 2);
    s += __shfl_xor_sync(FULL, s, 1);

    float inv = __fdividef(1.0f, s);   // row (lane>>2)&7's new q

    // Gather the pair this lane will ship: rows 2*idx, 2*idx+1 (idx = lane&3)
    int idx = lane & 3;
    float va = __shfl_sync(FULL, inv, idx * 8);
    float vb = __shfl_sync(FULL, inv, idx * 8 + 4);

    // Ship to dest CTA (lane>>2): 8 bytes, completion rides with the store
    {
        unsigned dest = (unsigned)(lane >> 2);
        uint32_t dst = qdst_sm + (uint32_t)(row0 + 2 * idx) * 4u;
        uint32_t barw = (rank < 4) ? barA_w : barB_w;
        uint32_t rd, rb;
        asm volatile("mapa.shared::cluster.u32 %0, %1, %2;"
                     : "=r"(rd) : "r"(dst), "r"(dest));
        asm volatile("mapa.shared::cluster.u32 %0, %1, %2;"
                     : "=r"(rb) : "r"(barw), "r"(dest));
        asm volatile(
            "st.async.shared::cluster.mbarrier::complete_tx::bytes.v2.b32 "
            "[%0], {%1, %2}, [%3];"
            :: "r"(rd), "r"(__float_as_uint(va)), "r"(__float_as_uint(vb)), "r"(rb)
            : "memory");
    }
}

// ---------------------------------------------------------------------------
// Persistent iteration kernel (prep fused): one 8-CTA cluster per batch.
// ---------------------------------------------------------------------------
__global__ void __launch_bounds__(256, 1) iter_kernel(const float* __restrict__ xp,
                                                      const float* __restrict__ xu) {
    __shared__ __align__(16) float qbuf0[D];
    __shared__ __align__(16) float qbuf1[D];
    __shared__ __align__(8) u64 barmem[4];   // A0, B0, A1, B1

    unsigned rank;
    asm("mov.u32 %0, %%cluster_ctarank;" : "=r"(rank));
    const int batch = blockIdx.x >> 3;
    const int tid   = threadIdx.x;
    const int wid   = tid >> 5;
    const int lane  = tid & 31;
    const int row0  = (int)rank * 64 + wid * 8;

    // ---- Fused prep: build K fragment from xp/xu, also store to g_K ----
    // kf[r][m] = packed (K[i][j], K[i][j+1]), i = row0+r, j = 2*lane + 64m
    u64 kf[8][8];
    {
        const float* xpb = xp + (size_t)batch * LDIM * LDIM;
        const float* xub = xu + (size_t)batch * LDIM;
        float* Kb = g_K + (size_t)batch * D * D;
        #pragma unroll
        for (int r = 0; r < 8; r++) {
            int i = row0 + r;
            const float* rowp = xpb + (size_t)(1 + i) * LDIM + 1;
            float dv = xub[1 + i];
            #pragma unroll
            for (int m = 0; m < 8; m++) {
                int j = 2 * lane + 64 * m;
                float a0 = rowp[j];
                float a1 = rowp[j + 1];
                float t0 = xpb[(size_t)(1 + j) * LDIM + 1 + i];
                float t1 = xpb[(size_t)(2 + j) * LDIM + 1 + i];
                float v0 = 0.5f * (a0 + t0);
                float v1 = 0.5f * (a1 + t1);
                if (j == i)     v0 = dv;
                if (j + 1 == i) v1 = dv;
                float e0 = expf(v0);
                float e1 = expf(v1);
                kf[r][m] = pack2(e0, e1);
                *(float2*)(Kb + (size_t)i * D + j) = make_float2(e0, e1);
            }
        }
    }

    qbuf0[tid]       = 1.0f;
    qbuf0[tid + 256] = 1.0f;

    const uint32_t q0 = (uint32_t)__cvta_generic_to_shared(qbuf0);
    const uint32_t q1 = (uint32_t)__cvta_generic_to_shared(qbuf1);
    const uint32_t A0 = (uint32_t)__cvta_generic_to_shared(&barmem[0]);
    const uint32_t B0 = (uint32_t)__cvta_generic_to_shared(&barmem[1]);
    const uint32_t A1 = (uint32_t)__cvta_generic_to_shared(&barmem[2]);
    const uint32_t B1 = (uint32_t)__cvta_generic_to_shared(&barmem[3]);

    if (tid == 0) {
        asm volatile("mbarrier.init.shared.b64 [%0], 1;" :: "r"(A0) : "memory");
        asm volatile("mbarrier.init.shared.b64 [%0], 1;" :: "r"(B0) : "memory");
        asm volatile("mbarrier.init.shared.b64 [%0], 1;" :: "r"(A1) : "memory");
        asm volatile("mbarrier.init.shared.b64 [%0], 1;" :: "r"(B1) : "memory");
        asm volatile("fence.mbarrier_init.release.cluster;" ::: "memory");
    }
    __syncthreads();
    asm volatile("barrier.cluster.arrive.aligned;\n\t"
                 "barrier.cluster.wait.aligned;" ::: "memory");

    // Phases: buf0 barriers waited at it2=1..63 (+ final) -> parity (use-1)&1
    //         buf1 barriers waited at it2=0..63           -> parity  it2&1
    unsigned par0 = 0, par1 = 0;

    #pragma unroll 1
    for (int it2 = 0; it2 < NITER2; it2++) {
        // read buf0 -> write buf1
        halfstep(kf, qbuf0, A0, B0, par0, it2 > 0, q1, A1, B1,
                 tid, lane, rank, row0);
        if (it2 > 0) par0 ^= 1;
        // read buf1 -> write buf0
        halfstep(kf, qbuf1, A1, B1, par1, true, q0, A0, B0,
                 tid, lane, rank, row0);
        par1 ^= 1;
    }

    // Final: wait for the last buf0 ships (q_128)
    if (tid == 0) {
        asm volatile("mbarrier.arrive.expect_tx.shared.b64 _, [%0], 1024;"
                     :: "r"(A0) : "memory");
        asm volatile("mbarrier.arrive.expect_tx.shared.b64 _, [%0], 1024;"
                     :: "r"(B0) : "memory");
    }
    bar_wait(A0, par0);
    bar_wait(B0, par0);

    // qbuf0 = q_128 = exp(-u_64);  qbuf1 = q_127 = exp(-v_64)
    if (tid < 64) {
        int row = (int)rank * 64 + tid;
        g_qu[batch * D + row] = qbuf0[row];
        g_qv[batch * D + row] = qbuf1[row];
    }

    asm volatile("barrier.cluster.arrive.aligned;\n\t"
                 "barrier.cluster.wait.aligned;" ::: "memory");
}

// ---------------------------------------------------------------------------
// Writeback: xp output [0, 16*513*513) then xu output [.., +16*513)
// ---------------------------------------------------------------------------
__global__ void out_kernel(const float* __restrict__ xp,
                           const float* __restrict__ xu,
                           float* __restrict__ out) {
    int idx = blockIdx.x * blockDim.x + threadIdx.x;
    const int T1 = BATCH * LDIM * LDIM;
    const int T2 = BATCH * LDIM;
    if (idx < T1) {
        int b   = idx / (LDIM * LDIM);
        int rem = idx - b * (LDIM * LDIM);
        int i = rem / LDIM;
        int j = rem - i * LDIM;
        float v;
        if (i == 0 && j == 0)       v = expf(xp[idx]);
        else if (i == 0 || j == 0)  v = xp[idx];
        else if (i == j)            v = 0.0f;
        else {
            v = g_K[((size_t)b * D + (i - 1)) * D + (j - 1)]
                * g_qu[b * D + i - 1] * g_qv[b * D + j - 1];
        }
        out[idx] = v;
    } else if (idx < T1 + T2) {
        int k = idx - T1;
        int b = k / LDIM;
        int i = k - b * LDIM;
        float v;
        if (i == 0) v = expf(xu[k]);
        else {
            int d = i - 1;
            v = g_K[((size_t)b * D + d) * D + d]
                * g_qu[b * D + d] * g_qv[b * D + d];
        }
        out[idx] = v;
    }
}

// ---------------------------------------------------------------------------
extern "C" void kernel_launch(void* const* d_in, const int* in_sizes, int n_in,
                              void* d_out, int out_size) {
    const float* xp;
    const float* xu;
    if (in_sizes[0] >= in_sizes[1]) { xp = (const float*)d_in[0]; xu = (const float*)d_in[1]; }
    else                            { xp = (const float*)d_in[1]; xu = (const float*)d_in[0]; }
    float* out = (float*)d_out;

    // 1) 128 Sinkhorn half-steps (prep fused), one 8-CTA cluster per batch
    cudaLaunchConfig_t cfg = {};
    cfg.gridDim  = dim3(BATCH * 8);
    cfg.blockDim = dim3(256);
    cfg.dynamicSmemBytes = 0;
    cfg.stream = 0;
    cudaLaunchAttribute attrs[1];
    attrs[0].id = cudaLaunchAttributeClusterDimension;
    attrs[0].val.clusterDim.x = 8;
    attrs[0].val.clusterDim.y = 1;
    attrs[0].val.clusterDim.z = 1;
    cfg.attrs = attrs;
    cfg.numAttrs = 1;
    cudaLaunchKernelEx(&cfg, iter_kernel, xp, xu);

    // 2) Writeback
    const int total = BATCH * LDIM * LDIM + BATCH * LDIM;
    out_kernel<<<(total + 255) / 256, 256>>>(xp, xu, out);
}

// round 8
// speedup vs baseline: 2.0952x; 1.0110x over previous
#include <cuda_runtime.h>
#include <cstdint>

typedef unsigned long long u64;

#define BATCH 16
#define D 512
#define LDIM 513
#define NITER2 64   // 64 iteration-pairs = 128 half-steps

__device__ float g_K[(size_t)BATCH * D * D];   // K = exp(symmetrized w0), for writeback
__device__ float g_qu[BATCH * D];
__device__ float g_qv[BATCH * D];

// ---------------------------------------------------------------------------
// Packed f32x2 helpers
// ---------------------------------------------------------------------------
__device__ __forceinline__ u64 fma2(u64 a, u64 b, u64 c) {
    u64 d;
    asm("fma.rn.f32x2 %0, %1, %2, %3;" : "=l"(d) : "l"(a), "l"(b), "l"(c));
    return d;
}
__device__ __forceinline__ u64 pack2(float x, float y) {
    u64 d;
    asm("mov.b64 %0, {%1, %2};" : "=l"(d) : "f"(x), "f"(y));
    return d;
}

// try_wait, CTA-scope acquire (async-proxy stores into our SMEM are ordered
// by complete_tx; cluster-scope acquire is unnecessary and expensive)
__device__ __forceinline__ void bar_wait(uint32_t bar, unsigned ph) {
    unsigned done;
    asm volatile(
        "{\n\t.reg .pred p;\n\t"
        "mbarrier.try_wait.parity.acquire.cta.shared::cta.b64 p, [%1], %2;\n\t"
        "selp.b32 %0, 1, 0, p;\n\t}"
        : "=r"(done) : "r"(bar), "r"(ph) : "memory");
    while (!done) {
        asm volatile(
            "{\n\t.reg .pred p;\n\t"
            "mbarrier.try_wait.parity.acquire.cta.shared::cta.b64 p, [%1], %2, 0x989680;\n\t"
            "selp.b32 %0, 1, 0, p;\n\t}"
            : "=r"(done) : "r"(bar), "r"(ph) : "memory");
    }
}

// ---------------------------------------------------------------------------
// One half-step. Remote addresses (rd = data slot in dest CTA's write buffer,
// rbw = dest CTA's write barrier) are precomputed and loop-invariant.
// ---------------------------------------------------------------------------
__device__ __forceinline__ void halfstep(const u64 (&kf)[8][8],
                                         const float* __restrict__ qsrc,
                                         uint32_t barA_r, uint32_t barB_r,
                                         unsigned ph, bool do_wait,
                                         uint32_t rd, uint32_t rbw,
                                         int tid, int lane) {
    if (do_wait && tid == 0) {
        asm volatile("mbarrier.arrive.expect_tx.shared.b64 _, [%0], 1024;"
                     :: "r"(barA_r) : "memory");
        asm volatile("mbarrier.arrive.expect_tx.shared.b64 _, [%0], 1024;"
                     :: "r"(barB_r) : "memory");
    }

    u64 acc64[8];
    #pragma unroll
    for (int r = 0; r < 8; r++) acc64[r] = 0ULL;

    if (do_wait) bar_wait(barA_r, ph);
    #pragma unroll
    for (int m = 0; m < 4; m++) {
        float2 qq = *(const float2*)(qsrc + m * 64 + 2 * lane);
        u64 qp = pack2(qq.x, qq.y);
        #pragma unroll
        for (int r = 0; r < 8; r++) acc64[r] = fma2(kf[r][m], qp, acc64[r]);
    }
    if (do_wait) bar_wait(barB_r, ph);
    #pragma unroll
    for (int m = 4; m < 8; m++) {
        float2 qq = *(const float2*)(qsrc + m * 64 + 2 * lane);
        u64 qp = pack2(qq.x, qq.y);
        #pragma unroll
        for (int r = 0; r < 8; r++) acc64[r] = fma2(kf[r][m], qp, acc64[r]);
    }

    float acc[8];
    #pragma unroll
    for (int r = 0; r < 8; r++) {
        unsigned lo, hi;
        asm("mov.b64 {%0, %1}, %2;" : "=r"(lo), "=r"(hi) : "l"(acc64[r]));
        acc[r] = __uint_as_float(lo) + __uint_as_float(hi);
    }

    // Folded butterfly: lane ends with the full sum for row (lane>>2)&7
    const unsigned FULL = 0xffffffffu;
    bool hi4 = (lane & 16) != 0;
    float v[4];
    #pragma unroll
    for (int i = 0; i < 4; i++) {
        float t = hi4 ? acc[i] : acc[4 + i];
        float r = __shfl_xor_sync(FULL, t, 16);
        v[i] = (hi4 ? acc[4 + i] : acc[i]) + r;
    }
    bool hi3 = (lane & 8) != 0;
    float w[2];
    #pragma unroll
    for (int i = 0; i < 2; i++) {
        float t = hi3 ? v[i] : v[2 + i];
        float r = __shfl_xor_sync(FULL, t, 8);
        w[i] = (hi3 ? v[2 + i] : v[i]) + r;
    }
    bool hi2 = (lane & 4) != 0;
    {
        float t = hi2 ? w[0] : w[1];
        float r = __shfl_xor_sync(FULL, t, 4);
        w[0] = (hi2 ? w[1] : w[0]) + r;
    }
    float s = w[0];
    s += __shfl_xor_sync(FULL, s, 2);
    s += __shfl_xor_sync(FULL, s, 1);

    float inv = __fdividef(1.0f, s);   // row (lane>>2)&7's new q

    // Gather the pair this lane ships: rows 2*idx, 2*idx+1 (idx = lane&3)
    int idx = lane & 3;
    float va = __shfl_sync(FULL, inv, idx * 8);
    float vb = __shfl_sync(FULL, inv, idx * 8 + 4);

    // Ship to dest CTA (lane>>2); completion rides with the store
    asm volatile(
        "st.async.shared::cluster.mbarrier::complete_tx::bytes.v2.b32 "
        "[%0], {%1, %2}, [%3];"
        :: "r"(rd), "r"(__float_as_uint(va)), "r"(__float_as_uint(vb)), "r"(rbw)
        : "memory");
}

// ---------------------------------------------------------------------------
// Persistent iteration kernel (prep fused): one 8-CTA cluster per batch.
// ---------------------------------------------------------------------------
__global__ void __launch_bounds__(256, 1) iter_kernel(const float* __restrict__ xp,
                                                      const float* __restrict__ xu) {
    __shared__ __align__(16) float qbuf0[D];
    __shared__ __align__(16) float qbuf1[D];
    __shared__ __align__(8) u64 barmem[4];   // A0, B0, A1, B1

    unsigned rank;
    asm("mov.u32 %0, %%cluster_ctarank;" : "=r"(rank));
    const int batch = blockIdx.x >> 3;
    const int tid   = threadIdx.x;
    const int wid   = tid >> 5;
    const int lane  = tid & 31;
    const int row0  = (int)rank * 64 + wid * 8;

    // ---- Fused prep: build K fragment from xp/xu, also store to g_K ----
    u64 kf[8][8];
    {
        const float* xpb = xp + (size_t)batch * LDIM * LDIM;
        const float* xub = xu + (size_t)batch * LDIM;
        float* Kb = g_K + (size_t)batch * D * D;
        #pragma unroll
        for (int r = 0; r < 8; r++) {
            int i = row0 + r;
            const float* rowp = xpb + (size_t)(1 + i) * LDIM + 1;
            float dv = xub[1 + i];
            #pragma unroll
            for (int m = 0; m < 8; m++) {
                int j = 2 * lane + 64 * m;
                float a0 = rowp[j];
                float a1 = rowp[j + 1];
                float t0 = xpb[(size_t)(1 + j) * LDIM + 1 + i];
                float t1 = xpb[(size_t)(2 + j) * LDIM + 1 + i];
                float v0 = 0.5f * (a0 + t0);
                float v1 = 0.5f * (a1 + t1);
                if (j == i)     v0 = dv;
                if (j + 1 == i) v1 = dv;
                float e0 = expf(v0);
                float e1 = expf(v1);
                kf[r][m] = pack2(e0, e1);
                *(float2*)(Kb + (size_t)i * D + j) = make_float2(e0, e1);
            }
        }
    }

    qbuf0[tid]       = 1.0f;
    qbuf0[tid + 256] = 1.0f;

    const uint32_t q0 = (uint32_t)__cvta_generic_to_shared(qbuf0);
    const uint32_t q1 = (uint32_t)__cvta_generic_to_shared(qbuf1);
    const uint32_t A0 = (uint32_t)__cvta_generic_to_shared(&barmem[0]);
    const uint32_t B0 = (uint32_t)__cvta_generic_to_shared(&barmem[1]);
    const uint32_t A1 = (uint32_t)__cvta_generic_to_shared(&barmem[2]);
    const uint32_t B1 = (uint32_t)__cvta_generic_to_shared(&barmem[3]);

    if (tid == 0) {
        asm volatile("mbarrier.init.shared.b64 [%0], 1;" :: "r"(A0) : "memory");
        asm volatile("mbarrier.init.shared.b64 [%0], 1;" :: "r"(B0) : "memory");
        asm volatile("mbarrier.init.shared.b64 [%0], 1;" :: "r"(A1) : "memory");
        asm volatile("mbarrier.init.shared.b64 [%0], 1;" :: "r"(B1) : "memory");
        asm volatile("fence.mbarrier_init.release.cluster;" ::: "memory");
    }

    // Precompute loop-invariant remote addresses for this lane's ship
    unsigned dest = (unsigned)(lane >> 2);
    int idx = lane & 3;
    uint32_t dloc0 = q0 + (uint32_t)(row0 + 2 * idx) * 4u;
    uint32_t dloc1 = q1 + (uint32_t)(row0 + 2 * idx) * 4u;
    uint32_t bw0 = (rank < 4) ? A0 : B0;
    uint32_t bw1 = (rank < 4) ? A1 : B1;
    uint32_t rd0, rd1, rb0, rb1;
    asm("mapa.shared::cluster.u32 %0, %1, %2;" : "=r"(rd0) : "r"(dloc0), "r"(dest));
    asm("mapa.shared::cluster.u32 %0, %1, %2;" : "=r"(rd1) : "r"(dloc1), "r"(dest));
    asm("mapa.shared::cluster.u32 %0, %1, %2;" : "=r"(rb0) : "r"(bw0), "r"(dest));
    asm("mapa.shared::cluster.u32 %0, %1, %2;" : "=r"(rb1) : "r"(bw1), "r"(dest));

    __syncthreads();
    asm volatile("barrier.cluster.arrive.aligned;\n\t"
                 "barrier.cluster.wait.aligned;" ::: "memory");

    unsigned par0 = 0, par1 = 0;

    #pragma unroll 1
    for (int it2 = 0; it2 < NITER2; it2++) {
        // read buf0 -> write buf1
        halfstep(kf, qbuf0, A0, B0, par0, it2 > 0, rd1, rb1, tid, lane);
        if (it2 > 0) par0 ^= 1;
        // read buf1 -> write buf0
        halfstep(kf, qbuf1, A1, B1, par1, true, rd0, rb0, tid, lane);
        par1 ^= 1;
    }

    // Final: wait for the last buf0 ships (q_128)
    if (tid == 0) {
        asm volatile("mbarrier.arrive.expect_tx.shared.b64 _, [%0], 1024;"
                     :: "r"(A0) : "memory");
        asm volatile("mbarrier.arrive.expect_tx.shared.b64 _, [%0], 1024;"
                     :: "r"(B0) : "memory");
    }
    bar_wait(A0, par0);
    bar_wait(B0, par0);

    // qbuf0 = q_128 = exp(-u_64);  qbuf1 = q_127 = exp(-v_64)
    if (tid < 64) {
        int row = (int)rank * 64 + tid;
        g_qu[batch * D + row] = qbuf0[row];
        g_qv[batch * D + row] = qbuf1[row];
    }

    asm volatile("barrier.cluster.arrive.aligned;\n\t"
                 "barrier.cluster.wait.aligned;" ::: "memory");
}

// ---------------------------------------------------------------------------
// Writeback, division-free 2D grid:
//   blockIdx.y encodes (batch, row r in 0..513); r==513 -> the xu row.
// ---------------------------------------------------------------------------
__global__ void out_kernel(const float* __restrict__ xp,
                           const float* __restrict__ xu,
                           float* __restrict__ out) {
    const int br = blockIdx.y;
    const int b  = br / (LDIM + 1);          // uniform per block
    const int r  = br - b * (LDIM + 1);
    const int j  = blockIdx.x * blockDim.x + threadIdx.x;
    if (j >= LDIM) return;

    if (r < LDIM) {
        size_t idx = ((size_t)b * LDIM + r) * LDIM + j;
        float v;
        if (r == 0 && j == 0)       v = expf(xp[idx]);
        else if (r == 0 || j == 0)  v = xp[idx];
        else if (r == j)            v = 0.0f;
        else {
            v = g_K[((size_t)b * D + (r - 1)) * D + (j - 1)]
                * g_qu[b * D + r - 1] * g_qv[b * D + j - 1];
        }
        out[idx] = v;
    } else {
        size_t T1 = (size_t)BATCH * LDIM * LDIM;
        int k = b * LDIM + j;
        float v;
        if (j == 0) v = expf(xu[k]);
        else {
            int d = j - 1;
            v = g_K[((size_t)b * D + d) * D + d]
                * g_qu[b * D + d] * g_qv[b * D + d];
        }
        out[T1 + k] = v;
    }
}

// ---------------------------------------------------------------------------
extern "C" void kernel_launch(void* const* d_in, const int* in_sizes, int n_in,
                              void* d_out, int out_size) {
    const float* xp;
    const float* xu;
    if (in_sizes[0] >= in_sizes[1]) { xp = (const float*)d_in[0]; xu = (const float*)d_in[1]; }
    else                            { xp = (const float*)d_in[1]; xu = (const float*)d_in[0]; }
    float* out = (float*)d_out;

    // 1) 128 Sinkhorn half-steps (prep fused), one 8-CTA cluster per batch
    cudaLaunchConfig_t cfg = {};
    cfg.gridDim  = dim3(BATCH * 8);
    cfg.blockDim = dim3(256);
    cfg.dynamicSmemBytes = 0;
    cfg.stream = 0;
    cudaLaunchAttribute attrs[1];
    attrs[0].id = cudaLaunchAttributeClusterDimension;
    attrs[0].val.clusterDim.x = 8;
    attrs[0].val.clusterDim.y = 1;
    attrs[0].val.clusterDim.z = 1;
    cfg.attrs = attrs;
    cfg.numAttrs = 1;
    cudaLaunchKernelEx(&cfg, iter_kernel, xp, xu);

    // 2) Writeback (division-free 2D grid)
    dim3 og((LDIM + 255) / 256, BATCH * (LDIM + 1));
    out_kernel<<<og, 256>>>(xp, xu, out);
}